// round 8
// baseline (speedup 1.0000x reference)
#include <cuda_runtime.h>
#include <cuda_bf16.h>

// CPTensor reconstruction as GEMM:
//   out[(i0*256 + i2)*512 + i1] = sum_r f0[i0,r]*f2[i2,r]*f1[i1,r]
//   => C[M=131072, N=512] = A[M,32] * B[512,32]^T,  A[m,r] = f0[m/256,r]*f2[m%256,r]
// Classic smem-tiled GEMM, r-major (transposed) smem tiles, 8x8 register tile
// per thread, packed fp32x2 FMAs (Blackwell f32x2 pipe) to halve FFMA issue count.

#define CP_N0 512
#define CP_N1 512
#define CP_N2 256
#define CP_R  32
#define BM    128
#define BN    128

__device__ __forceinline__ void ffma2(unsigned long long& d,
                                      unsigned long long a,
                                      unsigned long long b) {
    asm("fma.rn.f32x2 %0, %1, %2, %3;" : "=l"(d) : "l"(a), "l"(b), "l"(d));
}

__device__ __forceinline__ unsigned long long bcast2(float x) {
    unsigned long long r;
    unsigned int xi = __float_as_uint(x);
    asm("mov.b64 %0, {%1, %1};" : "=l"(r) : "r"(xi));
    return r;
}

__global__ __launch_bounds__(256, 2)
void cp_recon_kernel(const float* __restrict__ f0,
                     const float* __restrict__ f1,
                     const float* __restrict__ f2,
                     float* __restrict__ out) {
    __shared__ float As[CP_R][BM];   // A tile, r-major: As[r][m_local]
    __shared__ float Bs[CP_R][BN];   // f1 tile, r-major: Bs[r][n_local]

    const int bn   = blockIdx.x;          // 0..3   (n tiles)
    const int bm   = blockIdx.y;          // 0..1023 (m tiles)
    const int i0   = bm >> 1;             // 256 % BM == 0 -> one i0 per tile
    const int i2_0 = (bm & 1) * BM;
    const int n0   = bn * BN;
    const int tid  = threadIdx.x;

    // ---- Fill Bs: transpose f1[n0:n0+128, 0:32] into Bs[r][n] (16 elems/thread)
    #pragma unroll
    for (int k = 0; k < (BN * CP_R) / 256; k++) {
        int idx = k * 256 + tid;
        int n = idx >> 5;          // idx / 32
        int r = idx & 31;          // idx % 32
        Bs[r][n] = f1[(n0 + n) * CP_R + r];
    }
    // ---- Fill As: (f0 row) ⊙ (f2 slab), transposed into As[r][m]
    #pragma unroll
    for (int k = 0; k < (BM * CP_R) / 256; k++) {
        int idx = k * 256 + tid;
        int m = idx >> 5;
        int r = idx & 31;
        As[r][m] = f0[i0 * CP_R + r] * f2[(i2_0 + m) * CP_R + r];
    }
    __syncthreads();

    const int tx = tid & 15;   // n direction, 16 threads
    const int ty = tid >> 4;   // m direction, 16 threads

    // 8 rows x 8 cols per thread, cols held as 4 packed f32x2 accumulators.
    unsigned long long acc[8][4];
    #pragma unroll
    for (int i = 0; i < 8; i++)
        #pragma unroll
        for (int j = 0; j < 4; j++) acc[i][j] = 0ULL;

    #pragma unroll
    for (int r = 0; r < CP_R; r++) {
        // b: 8 consecutive f1 values = 4 f32x2, via two LDS.128 (conflict-free)
        const ulonglong2 b01 = *reinterpret_cast<const ulonglong2*>(&Bs[r][tx * 8]);
        const ulonglong2 b23 = *reinterpret_cast<const ulonglong2*>(&Bs[r][tx * 8 + 4]);
        // a: 8 consecutive A values, two LDS.128 (broadcast across tx -> conflict-free)
        const float4 aLo = *reinterpret_cast<const float4*>(&As[r][ty * 8]);
        const float4 aHi = *reinterpret_cast<const float4*>(&As[r][ty * 8 + 4]);
        const float av[8] = {aLo.x, aLo.y, aLo.z, aLo.w,
                             aHi.x, aHi.y, aHi.z, aHi.w};
        #pragma unroll
        for (int i = 0; i < 8; i++) {
            const unsigned long long a2 = bcast2(av[i]);
            ffma2(acc[i][0], a2, b01.x);
            ffma2(acc[i][1], a2, b01.y);
            ffma2(acc[i][2], a2, b23.x);
            ffma2(acc[i][3], a2, b23.y);
        }
    }

    // ---- Store 8x8 tile: rows m = bm*BM + ty*8 + i, cols [n0 + tx*8, +8)
    // Packed f32x2 lane order (lo = lower address) matches row-major memory.
    const size_t rowBase = (size_t)(bm * BM + ty * 8) * CP_N1 + n0 + tx * 8;
    #pragma unroll
    for (int i = 0; i < 8; i++) {
        ulonglong2* p = reinterpret_cast<ulonglong2*>(out + rowBase + (size_t)i * CP_N1);
        p[0] = make_ulonglong2(acc[i][0], acc[i][1]);
        p[1] = make_ulonglong2(acc[i][2], acc[i][3]);
    }
}

extern "C" void kernel_launch(void* const* d_in, const int* in_sizes, int n_in,
                              void* d_out, int out_size) {
    const float* f0 = (const float*)d_in[0];   // (512, 32)
    const float* f1 = (const float*)d_in[1];   // (512, 32)
    const float* f2 = (const float*)d_in[2];   // (256, 32)
    float* out = (float*)d_out;                // 512*256*512 fp32

    dim3 grid(CP_N1 / BN, (CP_N0 * CP_N2) / BM);   // (4, 1024)
    cp_recon_kernel<<<grid, 256>>>(f0, f1, f2, out);
}

// round 9
// speedup vs baseline: 1.1070x; 1.1070x over previous
#include <cuda_runtime.h>
#include <cuda_bf16.h>

// CPTensor reconstruction as GEMM:
//   out[(i0*256 + i2)*512 + i1] = sum_r f0[i0,r]*f2[i2,r]*f1[i1,r]
//   => C[M=131072, N=512] = A[M,32] * B[512,32]^T,  A[m,r] = f0[m/256,r]*f2[m%256,r]
//
// R8: retile 8x8 -> 16m x 4n per thread (warp = 8 tx * 4 ty) to cut L1/shared
// wavefronts ~3x (the 94.6%-utilized pipe in R7's profile):
//   B: one LDS.128/lane/r, 128B unique/warp  -> 1 wavefront (was 8)
//   A: 4x LDS.128/r, broadcast across tx     -> ~4 wavefronts (was 8)
// FMA work unchanged: packed fp32x2 FMAs.

#define CP_N0 512
#define CP_N1 512
#define CP_N2 256
#define CP_R  32
#define BM    128
#define BN    128

__device__ __forceinline__ void ffma2(unsigned long long& d,
                                      unsigned long long a,
                                      unsigned long long b) {
    asm("fma.rn.f32x2 %0, %1, %2, %3;" : "=l"(d) : "l"(a), "l"(b), "l"(d));
}

__device__ __forceinline__ unsigned long long bcast2(float x) {
    unsigned long long r;
    unsigned int xi = __float_as_uint(x);
    asm("mov.b64 %0, {%1, %1};" : "=l"(r) : "r"(xi));
    return r;
}

__global__ __launch_bounds__(256, 2)
void cp_recon_kernel(const float* __restrict__ f0,
                     const float* __restrict__ f1,
                     const float* __restrict__ f2,
                     float* __restrict__ out) {
    __shared__ float As[CP_R][BM];   // A tile, r-major: As[r][m_local]
    __shared__ float Bs[CP_R][BN];   // f1 tile, r-major: Bs[r][n_local]

    const int bn   = blockIdx.x;          // 0..3    (n tiles)
    const int bm   = blockIdx.y;          // 0..1023 (m tiles)
    const int i0   = bm >> 1;             // 256 % BM == 0 -> one i0 per tile
    const int i2_0 = (bm & 1) * BM;
    const int n0   = bn * BN;
    const int tid  = threadIdx.x;

    // ---- Fill Bs: transpose f1[n0:n0+128, 0:32] into Bs[r][n] (coalesced LDG)
    #pragma unroll
    for (int k = 0; k < (BN * CP_R) / 256; k++) {
        int idx = k * 256 + tid;
        int n = idx >> 5;          // idx / 32
        int r = idx & 31;          // idx % 32
        Bs[r][n] = f1[(n0 + n) * CP_R + r];
    }
    // ---- Fill As: (f0 row) ⊙ (f2 slab), transposed into As[r][m]
    #pragma unroll
    for (int k = 0; k < (BM * CP_R) / 256; k++) {
        int idx = k * 256 + tid;
        int m = idx >> 5;
        int r = idx & 31;
        As[r][m] = f0[i0 * CP_R + r] * f2[(i2_0 + m) * CP_R + r];
    }
    __syncthreads();

    // Warp layout: 8 warps as 2(m) x 4(n). Lane layout: 8(tx, n) x 4(ty, m).
    const int w      = tid >> 5;
    const int lane   = tid & 31;
    const int tx     = lane & 7;          // n dir: 8 lanes * 4 cols = 32 cols/warp
    const int ty     = lane >> 3;         // m dir: 4 lanes * 16 rows = 64 rows/warp
    const int warp_m = (w >> 2) * 64;     // 0 or 64
    const int warp_n = (w & 3) * 32;      // 0,32,64,96
    const int mloc   = warp_m + ty * 16;  // thread's first m-row in tile
    const int nloc   = warp_n + tx * 4;   // thread's first n-col in tile

    // 16 rows x 4 cols per thread; cols held as 2 packed f32x2 accumulators.
    unsigned long long acc[16][2];
    #pragma unroll
    for (int i = 0; i < 16; i++) { acc[i][0] = 0ULL; acc[i][1] = 0ULL; }

    #pragma unroll 4
    for (int r = 0; r < CP_R; r++) {
        // b: 4 consecutive f1 values = one LDS.128 (128B unique per warp -> 1 wf)
        const ulonglong2 b = *reinterpret_cast<const ulonglong2*>(&Bs[r][nloc]);
        // a: 16 consecutive A values, 4x LDS.128, broadcast across the 8 tx lanes
        const float4 a0 = *reinterpret_cast<const float4*>(&As[r][mloc +  0]);
        const float4 a1 = *reinterpret_cast<const float4*>(&As[r][mloc +  4]);
        const float4 a2 = *reinterpret_cast<const float4*>(&As[r][mloc +  8]);
        const float4 a3 = *reinterpret_cast<const float4*>(&As[r][mloc + 12]);
        const float av[16] = {a0.x, a0.y, a0.z, a0.w,
                              a1.x, a1.y, a1.z, a1.w,
                              a2.x, a2.y, a2.z, a2.w,
                              a3.x, a3.y, a3.z, a3.w};
        #pragma unroll
        for (int i = 0; i < 16; i++) {
            const unsigned long long a2b = bcast2(av[i]);
            ffma2(acc[i][0], a2b, b.x);
            ffma2(acc[i][1], a2b, b.y);
        }
    }

    // ---- Store 16x4 tile: rows m = bm*BM + mloc + i, cols [n0 + nloc, +4)
    // Packed f32x2 lane order (lo = lower address) matches row-major memory.
    const size_t rowBase = (size_t)(bm * BM + mloc) * CP_N1 + n0 + nloc;
    #pragma unroll
    for (int i = 0; i < 16; i++) {
        *reinterpret_cast<ulonglong2*>(out + rowBase + (size_t)i * CP_N1) =
            make_ulonglong2(acc[i][0], acc[i][1]);
    }
}

extern "C" void kernel_launch(void* const* d_in, const int* in_sizes, int n_in,
                              void* d_out, int out_size) {
    const float* f0 = (const float*)d_in[0];   // (512, 32)
    const float* f1 = (const float*)d_in[1];   // (512, 32)
    const float* f2 = (const float*)d_in[2];   // (256, 32)
    float* out = (float*)d_out;                // 512*256*512 fp32

    dim3 grid(CP_N1 / BN, (CP_N0 * CP_N2) / BM);   // (4, 1024)
    cp_recon_kernel<<<grid, 256>>>(f0, f1, f2, out);
}

// round 10
// speedup vs baseline: 1.8955x; 1.7122x over previous
#include <cuda_runtime.h>
#include <cuda_bf16.h>

// CPTensor reconstruction as GEMM:
//   out[(i0*256 + i2)*512 + i1] = sum_r f0[i0,r]*f2[i2,r]*f1[i1,r]
//   => C[M=131072, N=512] = A[M,32] * B[512,32]^T,  A[m,r] = f0[m/256,r]*f2[m%256,r]
//
// R9: the fill's transposed STS was 32-way bank-conflicted (8192 wf/CTA, the
// 81%-L1 culprit). New fill: thread owns one smem column, LDG.128 row loads,
// conflict-free STS.32. Also rotate per-ty A-load order in the mainloop to
// remove a 2-way LDS conflict. FMA work unchanged (packed fp32x2).

#define CP_N0 512
#define CP_N1 512
#define CP_N2 256
#define CP_R  32
#define BM    128
#define BN    128

__device__ __forceinline__ void ffma2(unsigned long long& d,
                                      unsigned long long a,
                                      unsigned long long b) {
    asm("fma.rn.f32x2 %0, %1, %2, %3;" : "=l"(d) : "l"(a), "l"(b), "l"(d));
}

__device__ __forceinline__ unsigned long long bcast2(float x) {
    unsigned long long r;
    unsigned int xi = __float_as_uint(x);
    asm("mov.b64 %0, {%1, %1};" : "=l"(r) : "r"(xi));
    return r;
}

__global__ __launch_bounds__(256, 2)
void cp_recon_kernel(const float* __restrict__ f0,
                     const float* __restrict__ f1,
                     const float* __restrict__ f2,
                     float* __restrict__ out) {
    __shared__ float As[CP_R][BM];   // A tile, r-major: As[r][m_local]
    __shared__ float Bs[CP_R][BN];   // f1 tile, r-major: Bs[r][n_local]

    const int bn   = blockIdx.x;          // 0..3    (n tiles)
    const int bm   = blockIdx.y;          // 0..1023 (m tiles)
    const int i0   = bm >> 1;             // 256 % BM == 0 -> one i0 per tile
    const int i2_0 = (bm & 1) * BM;
    const int n0   = bn * BN;
    const int tid  = threadIdx.x;

    // ---- Conflict-free fill: thread owns column `col`, r-half `rh`.
    // Within a warp all 32 lanes have distinct col -> STS bank = col%32, no conflicts.
    {
        const int col   = tid & 127;
        const int rbase = (tid >> 7) * 16;
        const float* s1 = f1 + (n0   + col) * CP_R + rbase;
        const float* s2 = f2 + (i2_0 + col) * CP_R + rbase;
        const float* s0 = f0 + i0 * CP_R + rbase;
        #pragma unroll
        for (int q = 0; q < 4; q++) {
            const float4 v1 = *reinterpret_cast<const float4*>(s1 + 4 * q);
            const float4 v2 = *reinterpret_cast<const float4*>(s2 + 4 * q);
            const float4 v0 = *reinterpret_cast<const float4*>(s0 + 4 * q);
            const int rr = rbase + 4 * q;
            Bs[rr + 0][col] = v1.x;  Bs[rr + 1][col] = v1.y;
            Bs[rr + 2][col] = v1.z;  Bs[rr + 3][col] = v1.w;
            As[rr + 0][col] = v2.x * v0.x;  As[rr + 1][col] = v2.y * v0.y;
            As[rr + 2][col] = v2.z * v0.z;  As[rr + 3][col] = v2.w * v0.w;
        }
    }
    __syncthreads();

    // Warp layout: 8 warps as 2(m) x 4(n). Lane layout: 8(tx, n) x 4(ty, m).
    const int w      = tid >> 5;
    const int lane   = tid & 31;
    const int tx     = lane & 7;          // n dir: 8 lanes * 4 cols = 32 cols/warp
    const int ty     = lane >> 3;         // m dir: 4 lanes * 16 rows = 64 rows/warp
    const int warp_m = (w >> 2) * 64;     // 0 or 64
    const int warp_n = (w & 3) * 32;      // 0,32,64,96
    const int mloc   = warp_m + ty * 16;  // thread's first m-row in tile
    const int nloc   = warp_n + tx * 4;   // thread's first n-col in tile

    // acc[j*4+c] accumulates row mloc + ((j+ty)&3)*4 + c  (ty-rotated mapping
    // makes the 4 A-loads per r hit 16 distinct banks -> conflict-free).
    unsigned long long acc[16][2];
    #pragma unroll
    for (int i = 0; i < 16; i++) { acc[i][0] = 0ULL; acc[i][1] = 0ULL; }

    #pragma unroll 4
    for (int r = 0; r < CP_R; r++) {
        // b: 4 consecutive f1 values = one LDS.128 (128B unique/warp -> 1 wf)
        const ulonglong2 b = *reinterpret_cast<const ulonglong2*>(&Bs[r][nloc]);
        // a: 4x LDS.128 with ty-rotated offsets -> all lane-addresses bank-distinct
        float4 a[4];
        #pragma unroll
        for (int j = 0; j < 4; j++) {
            const int off = ((j + ty) & 3) * 4;
            a[j] = *reinterpret_cast<const float4*>(&As[r][mloc + off]);
        }
        #pragma unroll
        for (int j = 0; j < 4; j++) {
            const float vv[4] = {a[j].x, a[j].y, a[j].z, a[j].w};
            #pragma unroll
            for (int c = 0; c < 4; c++) {
                const unsigned long long a2 = bcast2(vv[c]);
                ffma2(acc[j * 4 + c][0], a2, b.x);
                ffma2(acc[j * 4 + c][1], a2, b.y);
            }
        }
    }

    // ---- Store: acc[j*4+c] -> row mBlock + ((j+ty)&3)*4 + c, cols [n0+nloc, +4)
    const int mBlock = bm * BM + mloc;
    #pragma unroll
    for (int j = 0; j < 4; j++) {
        const int rowoff = ((j + ty) & 3) * 4;
        #pragma unroll
        for (int c = 0; c < 4; c++) {
            const size_t row = (size_t)(mBlock + rowoff + c);
            *reinterpret_cast<ulonglong2*>(out + row * CP_N1 + n0 + nloc) =
                make_ulonglong2(acc[j * 4 + c][0], acc[j * 4 + c][1]);
        }
    }
}

extern "C" void kernel_launch(void* const* d_in, const int* in_sizes, int n_in,
                              void* d_out, int out_size) {
    const float* f0 = (const float*)d_in[0];   // (512, 32)
    const float* f1 = (const float*)d_in[1];   // (512, 32)
    const float* f2 = (const float*)d_in[2];   // (256, 32)
    float* out = (float*)d_out;                // 512*256*512 fp32

    dim3 grid(CP_N1 / BN, (CP_N0 * CP_N2) / BM);   // (4, 1024)
    cp_recon_kernel<<<grid, 256>>>(f0, f1, f2, out);
}

// round 12
// speedup vs baseline: 2.1300x; 1.1237x over previous
#include <cuda_runtime.h>
#include <cuda_bf16.h>

// CPTensor reconstruction as GEMM:
//   out[(i0*256 + i2)*512 + i1] = sum_r f0[i0,r]*f2[i2,r]*f1[i1,r]
//   => C[M=131072, N=512] = A[M,32] * B[512,32]^T,  A[m,r] = f0[m/256,r]*f2[m%256,r]
//
// R10: fill was scattered-LDG bound (32 lines/warp-instr, ~3k wf/CTA). New fill
// reads the contiguous 16KB f1/f2 tiles with fully-coalesced LDG.128 and
// scatters via STS.32 into r-major smem with row stride 128+4 (4-way conflict
// max, mainloop alignment preserved). Mainloop/stores unchanged from R9.

#define CP_N0 512
#define CP_N1 512
#define CP_N2 256
#define CP_R  32
#define BM    128
#define BN    128
#define SPAD  4      // smem row pad: stride 132 keeps 16B alignment, kills 8-way

__device__ __forceinline__ void ffma2(unsigned long long& d,
                                      unsigned long long a,
                                      unsigned long long b) {
    asm("fma.rn.f32x2 %0, %1, %2, %3;" : "=l"(d) : "l"(a), "l"(b), "l"(d));
}

__device__ __forceinline__ unsigned long long bcast2(float x) {
    unsigned long long r;
    unsigned int xi = __float_as_uint(x);
    asm("mov.b64 %0, {%1, %1};" : "=l"(r) : "r"(xi));
    return r;
}

__global__ __launch_bounds__(256, 2)
void cp_recon_kernel(const float* __restrict__ f0,
                     const float* __restrict__ f1,
                     const float* __restrict__ f2,
                     float* __restrict__ out) {
    __shared__ float As[CP_R][BM + SPAD];   // A tile, r-major: As[r][m_local]
    __shared__ float Bs[CP_R][BN + SPAD];   // f1 tile, r-major: Bs[r][n_local]

    const int bn   = blockIdx.x;          // 0..3    (n tiles)
    const int bm   = blockIdx.y;          // 0..1023 (m tiles)
    const int i0   = bm >> 1;             // 256 % BM == 0 -> one i0 per tile
    const int i2_0 = (bm & 1) * BM;
    const int n0   = bn * BN;
    const int tid  = threadIdx.x;

    // ---- Coalesced fill. f1 tile and f2 slab are contiguous 16KB blocks:
    // thread t, iter q loads float4 #(q*256+t) -> row idx>>3, r-chunk (idx&7)*4.
    // idx&7 == tid&7, so the matching f0 chunk is loop-invariant per thread.
    {
        const int rc = (tid & 7) * 4;
        const float4 w = *reinterpret_cast<const float4*>(f0 + i0 * CP_R + rc);
        const float4* g1 = reinterpret_cast<const float4*>(f1 + n0   * CP_R);
        const float4* g2 = reinterpret_cast<const float4*>(f2 + i2_0 * CP_R);
        #pragma unroll
        for (int q = 0; q < 4; q++) {
            const int idx = q * 256 + tid;     // 0..1023 float4s per tile
            const int row = idx >> 3;          // 0..127
            const float4 v1 = g1[idx];
            const float4 v2 = g2[idx];
            Bs[rc + 0][row] = v1.x;  Bs[rc + 1][row] = v1.y;
            Bs[rc + 2][row] = v1.z;  Bs[rc + 3][row] = v1.w;
            As[rc + 0][row] = v2.x * w.x;  As[rc + 1][row] = v2.y * w.y;
            As[rc + 2][row] = v2.z * w.z;  As[rc + 3][row] = v2.w * w.w;
        }
    }
    __syncthreads();

    // Warp layout: 8 warps as 2(m) x 4(n). Lane layout: 8(tx, n) x 4(ty, m).
    const int w      = tid >> 5;
    const int lane   = tid & 31;
    const int tx     = lane & 7;          // n dir: 8 lanes * 4 cols = 32 cols/warp
    const int ty     = lane >> 3;         // m dir: 4 lanes * 16 rows = 64 rows/warp
    const int warp_m = (w >> 2) * 64;     // 0 or 64
    const int warp_n = (w & 3) * 32;      // 0,32,64,96
    const int mloc   = warp_m + ty * 16;  // thread's first m-row in tile
    const int nloc   = warp_n + tx * 4;   // thread's first n-col in tile

    // acc[j*4+c] accumulates row mloc + ((j+ty)&3)*4 + c  (ty-rotated mapping
    // keeps the 4 A-loads per r bank-distinct across the warp).
    unsigned long long acc[16][2];
    #pragma unroll
    for (int i = 0; i < 16; i++) { acc[i][0] = 0ULL; acc[i][1] = 0ULL; }

    #pragma unroll 4
    for (int r = 0; r < CP_R; r++) {
        // b: 4 consecutive f1 values = one LDS.128 (128B unique/warp -> 1 wf)
        const ulonglong2 b = *reinterpret_cast<const ulonglong2*>(&Bs[r][nloc]);
        // a: 4x LDS.128 with ty-rotated offsets -> lane addresses bank-distinct
        float4 a[4];
        #pragma unroll
        for (int j = 0; j < 4; j++) {
            const int off = ((j + ty) & 3) * 4;
            a[j] = *reinterpret_cast<const float4*>(&As[r][mloc + off]);
        }
        #pragma unroll
        for (int j = 0; j < 4; j++) {
            const float vv[4] = {a[j].x, a[j].y, a[j].z, a[j].w};
            #pragma unroll
            for (int c = 0; c < 4; c++) {
                const unsigned long long a2 = bcast2(vv[c]);
                ffma2(acc[j * 4 + c][0], a2, b.x);
                ffma2(acc[j * 4 + c][1], a2, b.y);
            }
        }
    }

    // ---- Store: acc[j*4+c] -> row mBlock + ((j+ty)&3)*4 + c, cols [n0+nloc, +4)
    const int mBlock = bm * BM + mloc;
    #pragma unroll
    for (int j = 0; j < 4; j++) {
        const int rowoff = ((j + ty) & 3) * 4;
        #pragma unroll
        for (int c = 0; c < 4; c++) {
            const size_t row = (size_t)(mBlock + rowoff + c);
            *reinterpret_cast<ulonglong2*>(out + row * CP_N1 + n0 + nloc) =
                make_ulonglong2(acc[j * 4 + c][0], acc[j * 4 + c][1]);
        }
    }
}

extern "C" void kernel_launch(void* const* d_in, const int* in_sizes, int n_in,
                              void* d_out, int out_size) {
    const float* f0 = (const float*)d_in[0];   // (512, 32)
    const float* f1 = (const float*)d_in[1];   // (512, 32)
    const float* f2 = (const float*)d_in[2];   // (256, 32)
    float* out = (float*)d_out;                // 512*256*512 fp32

    dim3 grid(CP_N1 / BN, (CP_N0 * CP_N2) / BM);   // (4, 1024)
    cp_recon_kernel<<<grid, 256>>>(f0, f1, f2, out);
}

// round 14
// speedup vs baseline: 2.9317x; 1.3764x over previous
#include <cuda_runtime.h>
#include <cuda_bf16.h>
#include <cstdint>

// CPTensor reconstruction via mma.sync (base-ISA HMMA — the harness compiles
// for virtual compute_103, so tcgen05 is unavailable; mma.sync/ldmatrix are
// sm_80-era base PTX and do compile).
//
//   out[(i0*256 + i2)*512 + i1] = sum_r f0[i0,r]*f2[i2,r]*f1[i1,r]
//   GEMM: C[m, n] = Q[m, 32] * P[n, 32]^T,  Q[m,:] = f0[i0,:] (*) f2[i2,:]
//
// bf16 2-way split: C = Qh*Ph + Qh*Pl + Ql*Ph  (error ~2^-16).
// A (Q) row-major k-contig -> ldmatrix x4 (a0..a3). B (P=f1) n-major k-contig
// is exactly the .col B-fragment layout -> ldmatrix x4 non-trans gives
// b0,b1 for two n-tiles at once. Smem rows padded to 80B: bank-conflict-free.

#define CP_R   32
#define BM     128          // m rows / CTA  (i2 block within one i0)
#define BN     128          // n cols / CTA
#define NTHREADS 256
#define RSTRIDE 80          // smem row stride in bytes (32 bf16 = 64B + 16B pad)

// smem tile offsets (bytes)
#define AH_OFF 0
#define AL_OFF (AH_OFF + BM * RSTRIDE)     // 10240
#define BH_OFF (AL_OFF + BM * RSTRIDE)     // 20480
#define BL_OFF (BH_OFF + BN * RSTRIDE)     // 30720
#define SM_BYTES (BL_OFF + BN * RSTRIDE)   // 40960 (static smem, <48KB)

static __device__ __forceinline__ uint32_t smem_u32(const void* p) {
    uint32_t a;
    asm("{ .reg .u64 t; cvta.to.shared.u64 t, %1; cvt.u32.u64 %0, t; }"
        : "=r"(a) : "l"(p));
    return a;
}

static __device__ __forceinline__ void ldsm_x4(uint32_t* r, uint32_t addr) {
    asm volatile("ldmatrix.sync.aligned.m8n8.x4.shared.b16 {%0,%1,%2,%3}, [%4];"
                 : "=r"(r[0]), "=r"(r[1]), "=r"(r[2]), "=r"(r[3]) : "r"(addr));
}

static __device__ __forceinline__ void mma_bf16(float* c, const uint32_t* a,
                                                uint32_t b0, uint32_t b1) {
    asm volatile(
        "mma.sync.aligned.m16n8k16.row.col.f32.bf16.bf16.f32 "
        "{%0,%1,%2,%3}, {%4,%5,%6,%7}, {%8,%9}, {%0,%1,%2,%3};"
        : "+f"(c[0]), "+f"(c[1]), "+f"(c[2]), "+f"(c[3])
        : "r"(a[0]), "r"(a[1]), "r"(a[2]), "r"(a[3]), "r"(b0), "r"(b1));
}

// split x,y into bf16 hi/lo packed pairs (lo16 = first element)
static __device__ __forceinline__ void split_pack(float x, float y,
                                                  uint32_t& hi, uint32_t& lo) {
    __nv_bfloat16 hx = __float2bfloat16_rn(x);
    __nv_bfloat16 hy = __float2bfloat16_rn(y);
    __nv_bfloat16 lx = __float2bfloat16_rn(x - __bfloat162float(hx));
    __nv_bfloat16 ly = __float2bfloat16_rn(y - __bfloat162float(hy));
    hi = (uint32_t)__bfloat16_as_ushort(hx) | ((uint32_t)__bfloat16_as_ushort(hy) << 16);
    lo = (uint32_t)__bfloat16_as_ushort(lx) | ((uint32_t)__bfloat16_as_ushort(ly) << 16);
}

__global__ __launch_bounds__(NTHREADS, 2)
void cp_mma_kernel(const float* __restrict__ f0,
                   const float* __restrict__ f1,
                   const float* __restrict__ f2,
                   float* __restrict__ out) {
    __shared__ char smem[SM_BYTES];
    const uint32_t sb = smem_u32(smem);

    const int tid  = threadIdx.x;
    const int bn   = blockIdx.x;          // 0..3
    const int bm   = blockIdx.y;          // 0..1023
    const int i0   = bm >> 1;
    const int i2_0 = (bm & 1) * BM;
    const int n0   = bn * BN;

    // ---- Fill smem tiles: coalesced LDG.128, bf16 hi/lo split, STS.64
    {
        const int kc = (tid & 7) * 4;                 // k chunk (idx&7 == tid&7)
        const float4 w4 = *reinterpret_cast<const float4*>(f0 + i0 * CP_R + kc);
        const float4* g2 = reinterpret_cast<const float4*>(f2 + (size_t)i2_0 * CP_R);
        const float4* g1 = reinterpret_cast<const float4*>(f1 + (size_t)n0 * CP_R);
        #pragma unroll
        for (int q = 0; q < (BM * CP_R / 4) / NTHREADS; q++) {
            const int idx = q * NTHREADS + tid;       // 0..1023 float4s
            const int row = idx >> 3;
            const uint32_t off = (uint32_t)row * RSTRIDE + (uint32_t)kc * 2u;
            // A = Q = f0 (*) f2
            const float4 v2 = g2[idx];
            uint32_t h01, l01, h23, l23;
            split_pack(v2.x * w4.x, v2.y * w4.y, h01, l01);
            split_pack(v2.z * w4.z, v2.w * w4.w, h23, l23);
            *reinterpret_cast<uint2*>(smem + AH_OFF + off) = make_uint2(h01, h23);
            *reinterpret_cast<uint2*>(smem + AL_OFF + off) = make_uint2(l01, l23);
            // B = P = f1
            const float4 v1 = g1[idx];
            split_pack(v1.x, v1.y, h01, l01);
            split_pack(v1.z, v1.w, h23, l23);
            *reinterpret_cast<uint2*>(smem + BH_OFF + off) = make_uint2(h01, h23);
            *reinterpret_cast<uint2*>(smem + BL_OFF + off) = make_uint2(l01, l23);
        }
    }
    __syncthreads();

    // ---- Warp tiling: 8 warps = 4(m) x 2(n); warp = 32 m-rows x 64 n-cols
    const int w    = tid >> 5;
    const int lane = tid & 31;
    const int wm   = (w >> 1) * 32;
    const int wn   = (w & 1) * 64;

    // ldmatrix per-lane addressing
    const int a_row = lane & 15;                         // A: rows 0..15
    const int a_kg  = (lane >> 4) * 8;                   // A: k sub 0/8
    const int b_n   = (lane & 7) + ((lane >> 4) << 3);   // B: n 0..15
    const int b_kg  = ((lane >> 3) & 1) * 8;             // B: k sub 0/8

    const uint32_t aAddr0 = sb + AH_OFF + (uint32_t)(wm + a_row) * RSTRIDE + a_kg * 2;
    const uint32_t aAddr1 = aAddr0 + 16 * RSTRIDE;
    const uint32_t bAddrBase = sb + BH_OFF + (uint32_t)(wn + b_n) * RSTRIDE + b_kg * 2;
    const uint32_t HL = (uint32_t)(AL_OFF - AH_OFF);     // hi->lo tile offset (10240)

    float acc[2][8][4];
    #pragma unroll
    for (int mt = 0; mt < 2; mt++)
        #pragma unroll
        for (int nt = 0; nt < 8; nt++)
            #pragma unroll
            for (int c = 0; c < 4; c++) acc[mt][nt][c] = 0.0f;

    #pragma unroll
    for (int ks = 0; ks < 2; ks++) {
        const uint32_t ko = ks * 32;                     // 16 bf16 = 32B per k-step
        uint32_t Ah[2][4], Al[2][4];
        ldsm_x4(Ah[0], aAddr0 + ko);
        ldsm_x4(Al[0], aAddr0 + HL + ko);
        ldsm_x4(Ah[1], aAddr1 + ko);
        ldsm_x4(Al[1], aAddr1 + HL + ko);
        #pragma unroll
        for (int np = 0; np < 4; np++) {                 // 4 n-pairs (2 tiles each)
            uint32_t Bh[4], Bl[4];
            const uint32_t ba = bAddrBase + (uint32_t)np * 16 * RSTRIDE + ko;
            ldsm_x4(Bh, ba);
            ldsm_x4(Bl, ba + HL);
            #pragma unroll
            for (int s = 0; s < 2; s++) {                // sub-tile within pair
                const int nt = np * 2 + s;
                #pragma unroll
                for (int mt = 0; mt < 2; mt++) {
                    mma_bf16(acc[mt][nt], Ah[mt], Bh[2 * s], Bh[2 * s + 1]); // Qh*Ph
                    mma_bf16(acc[mt][nt], Ah[mt], Bl[2 * s], Bl[2 * s + 1]); // Qh*Pl
                    mma_bf16(acc[mt][nt], Al[mt], Bh[2 * s], Bh[2 * s + 1]); // Ql*Ph
                }
            }
        }
    }

    // ---- Epilogue: D fragment c0,c1 -> (row gid, cols tig*2..+1); c2,c3 -> row+8
    const int gid = lane >> 2;
    const int tig = lane & 3;
    const size_t mG = (size_t)i0 * 256 + i2_0 + wm;
    #pragma unroll
    for (int mt = 0; mt < 2; mt++) {
        const size_t r0 = mG + mt * 16 + gid;
        #pragma unroll
        for (int nt = 0; nt < 8; nt++) {
            const int col = n0 + wn + nt * 8 + tig * 2;
            const float* c = acc[mt][nt];
            *reinterpret_cast<float2*>(out + r0 * 512 + col)       = make_float2(c[0], c[1]);
            *reinterpret_cast<float2*>(out + (r0 + 8) * 512 + col) = make_float2(c[2], c[3]);
        }
    }
}

extern "C" void kernel_launch(void* const* d_in, const int* in_sizes, int n_in,
                              void* d_out, int out_size) {
    const float* f0 = (const float*)d_in[0];   // (512, 32)
    const float* f1 = (const float*)d_in[1];   // (512, 32)
    const float* f2 = (const float*)d_in[2];   // (256, 32)
    float* out = (float*)d_out;                // 512*256*512 fp32

    dim3 grid(512 / BN, (512 * 256) / BM);     // (4, 1024)
    cp_mma_kernel<<<grid, NTHREADS>>>(f0, f1, f2, out);
}

// round 17
// speedup vs baseline: 3.1162x; 1.0629x over previous
#include <cuda_runtime.h>
#include <cuda_bf16.h>
#include <cstdint>

// CPTensor reconstruction via mma.sync (base-ISA HMMA; harness compiles for
// virtual compute_103 where tcgen05 is unavailable).
//
//   out[(i0*256 + i2)*512 + i1] = sum_r f0[i0,r]*f2[i2,r]*f1[i1,r]
//   GEMM: C[m, n] = Q[m, 32] * P[n, 32]^T,  Q[m,:] = f0[i0,:] (*) f2[i2,:]
//
// bf16 2-way split: C = Qh*Ph + Qh*Pl + Ql*Ph  (error ~2^-16).
// R14 profile: stores were 2048 L1-wf/CTA (STG.64 x 8 lines/instr) = the 71%
// L1 pipe. R15: butterfly-shuffle (tig ^ 1) packs 4 contiguous columns per
// lane -> STG.128, halving store instrs -> store wf 2048 -> ~1024+256 shfl.

#define CP_R   32
#define BM     128          // m rows / CTA  (i2 block within one i0)
#define BN     128          // n cols / CTA
#define NTHREADS 256
#define RSTRIDE 80          // smem row stride in bytes (32 bf16 = 64B + 16B pad)

// smem tile offsets (bytes)
#define AH_OFF 0
#define AL_OFF (AH_OFF + BM * RSTRIDE)     // 10240
#define BH_OFF (AL_OFF + BM * RSTRIDE)     // 20480
#define BL_OFF (BH_OFF + BN * RSTRIDE)     // 30720
#define SM_BYTES (BL_OFF + BN * RSTRIDE)   // 40960 (static smem, <48KB)

static __device__ __forceinline__ uint32_t smem_u32(const void* p) {
    uint32_t a;
    asm("{ .reg .u64 t; cvta.to.shared.u64 t, %1; cvt.u32.u64 %0, t; }"
        : "=r"(a) : "l"(p));
    return a;
}

static __device__ __forceinline__ void ldsm_x4(uint32_t* r, uint32_t addr) {
    asm volatile("ldmatrix.sync.aligned.m8n8.x4.shared.b16 {%0,%1,%2,%3}, [%4];"
                 : "=r"(r[0]), "=r"(r[1]), "=r"(r[2]), "=r"(r[3]) : "r"(addr));
}

static __device__ __forceinline__ void mma_bf16(float* c, const uint32_t* a,
                                                uint32_t b0, uint32_t b1) {
    asm volatile(
        "mma.sync.aligned.m16n8k16.row.col.f32.bf16.bf16.f32 "
        "{%0,%1,%2,%3}, {%4,%5,%6,%7}, {%8,%9}, {%0,%1,%2,%3};"
        : "+f"(c[0]), "+f"(c[1]), "+f"(c[2]), "+f"(c[3])
        : "r"(a[0]), "r"(a[1]), "r"(a[2]), "r"(a[3]), "r"(b0), "r"(b1));
}

// split x,y into bf16 hi/lo packed pairs (lo16 = first element)
static __device__ __forceinline__ void split_pack(float x, float y,
                                                  uint32_t& hi, uint32_t& lo) {
    __nv_bfloat16 hx = __float2bfloat16_rn(x);
    __nv_bfloat16 hy = __float2bfloat16_rn(y);
    __nv_bfloat16 lx = __float2bfloat16_rn(x - __bfloat162float(hx));
    __nv_bfloat16 ly = __float2bfloat16_rn(y - __bfloat162float(hy));
    hi = (uint32_t)__bfloat16_as_ushort(hx) | ((uint32_t)__bfloat16_as_ushort(hy) << 16);
    lo = (uint32_t)__bfloat16_as_ushort(lx) | ((uint32_t)__bfloat16_as_ushort(ly) << 16);
}

__global__ __launch_bounds__(NTHREADS, 2)
void cp_mma_kernel(const float* __restrict__ f0,
                   const float* __restrict__ f1,
                   const float* __restrict__ f2,
                   float* __restrict__ out) {
    __shared__ char smem[SM_BYTES];
    const uint32_t sb = smem_u32(smem);

    const int tid  = threadIdx.x;
    const int bn   = blockIdx.x;          // 0..3
    const int bm   = blockIdx.y;          // 0..1023
    const int i0   = bm >> 1;
    const int i2_0 = (bm & 1) * BM;
    const int n0   = bn * BN;

    // ---- Fill smem tiles: coalesced LDG.128, bf16 hi/lo split, STS.64
    {
        const int kc = (tid & 7) * 4;                 // k chunk (idx&7 == tid&7)
        const float4 w4 = *reinterpret_cast<const float4*>(f0 + i0 * CP_R + kc);
        const float4* g2 = reinterpret_cast<const float4*>(f2 + (size_t)i2_0 * CP_R);
        const float4* g1 = reinterpret_cast<const float4*>(f1 + (size_t)n0 * CP_R);
        #pragma unroll
        for (int q = 0; q < (BM * CP_R / 4) / NTHREADS; q++) {
            const int idx = q * NTHREADS + tid;       // 0..1023 float4s
            const int row = idx >> 3;
            const uint32_t off = (uint32_t)row * RSTRIDE + (uint32_t)kc * 2u;
            // A = Q = f0 (*) f2
            const float4 v2 = g2[idx];
            uint32_t h01, l01, h23, l23;
            split_pack(v2.x * w4.x, v2.y * w4.y, h01, l01);
            split_pack(v2.z * w4.z, v2.w * w4.w, h23, l23);
            *reinterpret_cast<uint2*>(smem + AH_OFF + off) = make_uint2(h01, h23);
            *reinterpret_cast<uint2*>(smem + AL_OFF + off) = make_uint2(l01, l23);
            // B = P = f1
            const float4 v1 = g1[idx];
            split_pack(v1.x, v1.y, h01, l01);
            split_pack(v1.z, v1.w, h23, l23);
            *reinterpret_cast<uint2*>(smem + BH_OFF + off) = make_uint2(h01, h23);
            *reinterpret_cast<uint2*>(smem + BL_OFF + off) = make_uint2(l01, l23);
        }
    }
    __syncthreads();

    // ---- Warp tiling: 8 warps = 4(m) x 2(n); warp = 32 m-rows x 64 n-cols
    const int w    = tid >> 5;
    const int lane = tid & 31;
    const int wm   = (w >> 1) * 32;
    const int wn   = (w & 1) * 64;

    // ldmatrix per-lane addressing
    const int a_row = lane & 15;                         // A: rows 0..15
    const int a_kg  = (lane >> 4) * 8;                   // A: k sub 0/8
    const int b_n   = (lane & 7) + ((lane >> 4) << 3);   // B: n 0..15
    const int b_kg  = ((lane >> 3) & 1) * 8;             // B: k sub 0/8

    const uint32_t aAddr0 = sb + AH_OFF + (uint32_t)(wm + a_row) * RSTRIDE + a_kg * 2;
    const uint32_t aAddr1 = aAddr0 + 16 * RSTRIDE;
    const uint32_t bAddrBase = sb + BH_OFF + (uint32_t)(wn + b_n) * RSTRIDE + b_kg * 2;
    const uint32_t HL = (uint32_t)(AL_OFF - AH_OFF);     // hi->lo tile offset (10240)

    float acc[2][8][4];
    #pragma unroll
    for (int mt = 0; mt < 2; mt++)
        #pragma unroll
        for (int nt = 0; nt < 8; nt++)
            #pragma unroll
            for (int c = 0; c < 4; c++) acc[mt][nt][c] = 0.0f;

    #pragma unroll
    for (int ks = 0; ks < 2; ks++) {
        const uint32_t ko = ks * 32;                     // 16 bf16 = 32B per k-step
        uint32_t Ah[2][4], Al[2][4];
        ldsm_x4(Ah[0], aAddr0 + ko);
        ldsm_x4(Al[0], aAddr0 + HL + ko);
        ldsm_x4(Ah[1], aAddr1 + ko);
        ldsm_x4(Al[1], aAddr1 + HL + ko);
        #pragma unroll
        for (int np = 0; np < 4; np++) {                 // 4 n-pairs (2 tiles each)
            uint32_t Bh[4], Bl[4];
            const uint32_t ba = bAddrBase + (uint32_t)np * 16 * RSTRIDE + ko;
            ldsm_x4(Bh, ba);
            ldsm_x4(Bl, ba + HL);
            #pragma unroll
            for (int s = 0; s < 2; s++) {                // sub-tile within pair
                const int nt = np * 2 + s;
                #pragma unroll
                for (int mt = 0; mt < 2; mt++) {
                    mma_bf16(acc[mt][nt], Ah[mt], Bh[2 * s], Bh[2 * s + 1]); // Qh*Ph
                    mma_bf16(acc[mt][nt], Ah[mt], Bl[2 * s], Bl[2 * s + 1]); // Qh*Pl
                    mma_bf16(acc[mt][nt], Al[mt], Bh[2 * s], Bh[2 * s + 1]); // Ql*Ph
                }
            }
        }
    }

    // ---- Epilogue: butterfly-pack to float4, STG.128 (halves store L1 wf).
    // Fragment: c0,c1 -> (row gid, cols nt*8 + tig*2 +0,1); c2,c3 -> row gid+8.
    // Lane pair tig ^ 1 swaps even-nt/odd-nt float2s so each lane assembles
    // 4 contiguous cols: base = p*16 + (tig&2)*2 + (tig&1)*8.
    const int gid = lane >> 2;
    const int tig = lane & 3;
    const int odd = tig & 1;
    const size_t mG = (size_t)i0 * 256 + i2_0 + wm;
    #pragma unroll
    for (int mt = 0; mt < 2; mt++) {
        #pragma unroll
        for (int rg = 0; rg < 2; rg++) {                 // rg0: c0c1, rg1: c2c3
            float* rowp = out + (mG + mt * 16 + rg * 8 + gid) * 512 + n0 + wn;
            #pragma unroll
            for (int p = 0; p < 4; p++) {
                const float* cE = acc[mt][2 * p];        // even nt (cols p*16+0..7)
                const float* cO = acc[mt][2 * p + 1];    // odd  nt (cols p*16+8..15)
                // even lanes send their odd-nt pair, odd lanes their even-nt pair
                const float s0 = odd ? cE[rg * 2 + 0] : cO[rg * 2 + 0];
                const float s1 = odd ? cE[rg * 2 + 1] : cO[rg * 2 + 1];
                const float r0 = __shfl_xor_sync(0xffffffffu, s0, 1);
                const float r1 = __shfl_xor_sync(0xffffffffu, s1, 1);
                float4 v;
                if (!odd) v = make_float4(cE[rg * 2 + 0], cE[rg * 2 + 1], r0, r1);
                else      v = make_float4(r0, r1, cO[rg * 2 + 0], cO[rg * 2 + 1]);
                const int colbase = p * 16 + (tig & 2) * 2 + odd * 8;
                *reinterpret_cast<float4*>(rowp + colbase) = v;
            }
        }
    }
}

extern "C" void kernel_launch(void* const* d_in, const int* in_sizes, int n_in,
                              void* d_out, int out_size) {
    const float* f0 = (const float*)d_in[0];   // (512, 32)
    const float* f1 = (const float*)d_in[1];   // (512, 32)
    const float* f2 = (const float*)d_in[2];   // (256, 32)
    float* out = (float*)d_out;                // 512*256*512 fp32

    dim3 grid(512 / BN, (512 * 256) / BM);     // (4, 1024)
    cp_mma_kernel<<<grid, NTHREADS>>>(f0, f1, f2, out);
}